// round 13
// baseline (speedup 1.0000x reference)
#include <cuda_runtime.h>
#include <cstdint>

#define NSEQ   1605
#define DIMF   1024
#define NH     16
#define DH     64
#define HWLEN  1600
#define PREFIX 5
#define NPAD   1664   // 26 * 64
#define NSPLIT 2
#define NKT_TOT 51
#define NKT0   26

// ---- scratch (device globals; zero-initialized at module load) ----
__device__ float g_q[(size_t)NH * NPAD * DH];
__device__ float g_k[(size_t)NH * NPAD * DH];
__device__ float g_v[(size_t)NH * NPAD * DH];
__device__ float g_attn[(size_t)NSEQ * DIMF];
__device__ float  g_part[(size_t)NSPLIT * NH * NPAD * DH];
__device__ float2 g_ml[(size_t)NSPLIT * NH * NPAD];

// ============================================================
// mma / ldmatrix helpers
// ============================================================
__device__ __forceinline__ uint32_t cvta_s(const void* p) {
    uint32_t a;
    asm("{ .reg .u64 t; cvta.to.shared.u64 t, %1; cvt.u32.u64 %0, t; }"
        : "=r"(a) : "l"(p));
    return a;
}

#define MMA_BF16(d, a0, a1, a2, a3, b0, b1) \
    asm volatile("mma.sync.aligned.m16n8k16.row.col.f32.bf16.bf16.f32 " \
        "{%0,%1,%2,%3}, {%4,%5,%6,%7}, {%8,%9}, {%0,%1,%2,%3};" \
        : "+f"((d)[0]), "+f"((d)[1]), "+f"((d)[2]), "+f"((d)[3]) \
        : "r"(a0), "r"(a1), "r"(a2), "r"(a3), "r"(b0), "r"(b1))

#define LDSM_X4(r0, r1, r2, r3, addr) \
    asm volatile("ldmatrix.sync.aligned.m8n8.x4.shared.b16 {%0,%1,%2,%3}, [%4];" \
        : "=r"(r0), "=r"(r1), "=r"(r2), "=r"(r3) : "r"(addr))

__device__ __forceinline__ uint32_t pack_bf16x2(float lo, float hi) {
    uint32_t w;
    asm("cvt.rn.bf16x2.f32 %0, %1, %2;" : "=r"(w) : "f"(hi), "f"(lo));
    return w;
}
__device__ __forceinline__ float lo_bf16(uint32_t w) { return __uint_as_float(w << 16); }
__device__ __forceinline__ float hi_bf16(uint32_t w) { return __uint_as_float(w & 0xFFFF0000u); }

__device__ __forceinline__ void split2(float e, float o, uint32_t& h, uint32_t& l) {
    h = pack_bf16x2(e, o);
    l = pack_bf16x2(e - lo_bf16(h), o - hi_bf16(h));
}

extern __shared__ float dynsm[];

// ============================================================
// bf16x3 GEMM mainloop (shared by qkv and proj):
// acc += A[bm:+128,0:1024] @ B[bn:+128,0:1024]^T, fp32-grade.
// packed bf16x2 hi/lo smem, double-buffered, ldmatrix loads.
// ============================================================
#define BST 12
#define BTILE (128 * BST)

__device__ __forceinline__ void gemm_db3b(
    const float* __restrict__ A, const float* __restrict__ B,
    int bm, int bn, int aRows, uint32_t* __restrict__ smem,
    float acc[4][4][4])
{
    const int tid = threadIdx.x;
    const int wid = tid >> 5, lane = tid & 31;
    const int warp_m = wid & 1, warp_n = wid >> 1;
    const int r0 = tid >> 2;
    const int f0 = (tid & 3) * 4;
    const int w0 = (tid & 3) * 2;

    const uint32_t smb = cvta_s(smem);
    const int a_lm = (warp_m * 64 + (lane & 15)) * BST + (lane >> 4) * 4;
    const int b_lm = (warp_n * 32 + (lane >> 4) * 8 + (lane & 7)) * BST
                     + ((lane >> 3) & 1) * 4;

    float4 pa[2], pb[2];

#define GB_LOAD(k0) do { \
    _Pragma("unroll") \
    for (int t = 0; t < 2; ++t) { \
        const int r = r0 + t * 64; \
        pa[t] = make_float4(0.f, 0.f, 0.f, 0.f); \
        if (bm + r < aRows) \
            pa[t] = *(const float4*)(A + (size_t)(bm + r) * 1024 + (k0) + f0); \
        pb[t] = *(const float4*)(B + (size_t)(bn + r) * 1024 + (k0) + f0); \
    } } while (0)

#define GB_STORE(bufp) do { \
    uint32_t* Ah_ = (bufp); \
    uint32_t* Al_ = (bufp) + BTILE; \
    uint32_t* Bh_ = (bufp) + 2 * BTILE; \
    uint32_t* Bl_ = (bufp) + 3 * BTILE; \
    _Pragma("unroll") \
    for (int t = 0; t < 2; ++t) { \
        const int r = r0 + t * 64; \
        uint32_t h0, l0, h1, l1; \
        split2(pa[t].x, pa[t].y, h0, l0); \
        split2(pa[t].z, pa[t].w, h1, l1); \
        Ah_[r * BST + w0] = h0; Ah_[r * BST + w0 + 1] = h1; \
        Al_[r * BST + w0] = l0; Al_[r * BST + w0 + 1] = l1; \
        split2(pb[t].x, pb[t].y, h0, l0); \
        split2(pb[t].z, pb[t].w, h1, l1); \
        Bh_[r * BST + w0] = h0; Bh_[r * BST + w0 + 1] = h1; \
        Bl_[r * BST + w0] = l0; Bl_[r * BST + w0 + 1] = l1; \
    } } while (0)

    GB_LOAD(0);
    GB_STORE(smem);
    __syncthreads();

    for (int c = 0; c < 64; ++c) {
        const int bufw = (c & 1) * (4 * BTILE);
        if (c < 63) GB_LOAD((c + 1) * 16);

        uint32_t ah[4][4], al[4][4];
#pragma unroll
        for (int mt = 0; mt < 4; ++mt) {
            LDSM_X4(ah[mt][0], ah[mt][1], ah[mt][2], ah[mt][3],
                    smb + (uint32_t)(bufw + a_lm + mt * 16 * BST) * 4u);
            LDSM_X4(al[mt][0], al[mt][1], al[mt][2], al[mt][3],
                    smb + (uint32_t)(bufw + BTILE + a_lm + mt * 16 * BST) * 4u);
        }
#pragma unroll
        for (int ntp = 0; ntp < 2; ++ntp) {
            uint32_t bh0, bh1, bh2, bh3, bl0, bl1, bl2, bl3;
            LDSM_X4(bh0, bh1, bh2, bh3,
                    smb + (uint32_t)(bufw + 2 * BTILE + b_lm + ntp * 16 * BST) * 4u);
            LDSM_X4(bl0, bl1, bl2, bl3,
                    smb + (uint32_t)(bufw + 3 * BTILE + b_lm + ntp * 16 * BST) * 4u);
#pragma unroll
            for (int mt = 0; mt < 4; ++mt) {
                MMA_BF16(acc[mt][2 * ntp], ah[mt][0], ah[mt][1], ah[mt][2], ah[mt][3], bh0, bh1);
                MMA_BF16(acc[mt][2 * ntp], ah[mt][0], ah[mt][1], ah[mt][2], ah[mt][3], bl0, bl1);
                MMA_BF16(acc[mt][2 * ntp], al[mt][0], al[mt][1], al[mt][2], al[mt][3], bh0, bh1);
                MMA_BF16(acc[mt][2 * ntp + 1], ah[mt][0], ah[mt][1], ah[mt][2], ah[mt][3], bh2, bh3);
                MMA_BF16(acc[mt][2 * ntp + 1], ah[mt][0], ah[mt][1], ah[mt][2], ah[mt][3], bl2, bl3);
                MMA_BF16(acc[mt][2 * ntp + 1], al[mt][0], al[mt][1], al[mt][2], al[mt][3], bh2, bh3);
            }
        }
        if (c < 63) GB_STORE(smem + ((c + 1) & 1) * (4 * BTILE));
        __syncthreads();
    }
#undef GB_LOAD
#undef GB_STORE
}

#define GSMEM_QK (2 * 4 * BTILE * 4)   // 49152 B

// ============================================================
// MERGED qkv GEMM: all columns bf16x3. grid (24, 13).
// bx<8 -> q (scaled 1/8), 8..15 -> k, 16..23 -> v
// ============================================================
__global__ __launch_bounds__(256, 2) void gemm_qkv_kern(
    const float* __restrict__ A, const float* __restrict__ B)
{
    const int bm = blockIdx.y * 128;
    const int bn = blockIdx.x * 128;
    const int tid = threadIdx.x;
    const int wid = tid >> 5, lane = tid & 31;
    const int warp_m = wid & 1, warp_n = wid >> 1;
    const int grp = lane >> 2, tig = lane & 3;

    float acc[4][4][4];
#pragma unroll
    for (int a = 0; a < 4; a++)
#pragma unroll
        for (int b = 0; b < 4; b++)
#pragma unroll
            for (int cc = 0; cc < 4; cc++) acc[a][b][cc] = 0.0f;

    gemm_db3b(A, B, bm, bn, NSEQ, (uint32_t*)dynsm, acc);

    const int s = bn >> 10;                   // 0=q, 1=k, 2=v
    float* __restrict__ dst = (s == 0) ? g_q : (s == 1) ? g_k : g_v;
    const float scale = (s == 0) ? 0.125f : 1.0f;

#pragma unroll
    for (int mt = 0; mt < 4; ++mt)
#pragma unroll
        for (int half = 0; half < 2; ++half) {
            const int row = bm + warp_m * 64 + mt * 16 + grp + half * 8;
            if (row >= NSEQ) continue;
#pragma unroll
            for (int nt = 0; nt < 4; ++nt) {
                const int col = bn + warp_n * 32 + nt * 8 + tig * 2;
                const int h = (col & 1023) >> 6;
                const int d = col & 63;
                float2 v;
                v.x = acc[mt][nt][half * 2 + 0] * scale;
                v.y = acc[mt][nt][half * 2 + 1] * scale;
                *(float2*)&dst[((size_t)h * NPAD + row) * DH + d] = v;
            }
        }
}

// ---- proj: bf16x3 + bias ----
__global__ __launch_bounds__(256, 2) void gemm_proj_kern(
    const float* __restrict__ B, const float* __restrict__ bias,
    float* __restrict__ C)
{
    const int bm = blockIdx.y * 128;
    const int bn = blockIdx.x * 128;
    float acc[4][4][4];
#pragma unroll
    for (int a = 0; a < 4; a++)
#pragma unroll
        for (int b = 0; b < 4; b++)
#pragma unroll
            for (int cc = 0; cc < 4; cc++) acc[a][b][cc] = 0.0f;

    gemm_db3b(g_attn, B, bm, bn, NSEQ, (uint32_t*)dynsm, acc);

    const int tid = threadIdx.x;
    const int wid = tid >> 5, lane = tid & 31;
    const int warp_m = wid & 1, warp_n = wid >> 1;
    const int grp = lane >> 2, tig = lane & 3;

#pragma unroll
    for (int mt = 0; mt < 4; ++mt)
#pragma unroll
        for (int half = 0; half < 2; ++half) {
            const int row = bm + warp_m * 64 + mt * 16 + grp + half * 8;
            if (row >= NSEQ) continue;
#pragma unroll
            for (int nt = 0; nt < 4; ++nt) {
                const int col = bn + warp_n * 32 + nt * 8 + tig * 2;
                float2 v;
                v.x = acc[mt][nt][half * 2 + 0] + bias[col];
                v.y = acc[mt][nt][half * 2 + 1] + bias[col + 1];
                *(float2*)&C[(size_t)row * 1024 + col] = v;
            }
        }
}

// ============================================================
// RoPE on q and k, rows PREFIX..NSEQ-1
// ============================================================
__global__ void rope_kernel(const float* __restrict__ rope)
{
    int idx = blockIdx.x * blockDim.x + threadIdx.x;
    if (idx >= HWLEN * NH * 32) return;
    const int d = idx & 31;
    const int h = (idx >> 5) & 15;
    const int p = idx >> 9;
    const int n = PREFIX + p;

    const float s0 = rope[p * 64 + d];
    const float s1 = rope[p * 64 + d + 32];
    const float c0 = rope[HWLEN * 64 + p * 64 + d];
    const float c1 = rope[HWLEN * 64 + p * 64 + d + 32];

    const size_t base = ((size_t)h * NPAD + n) * DH;

    float q0 = g_q[base + d], q1 = g_q[base + d + 32];
    g_q[base + d]      = q0 * c0 - q1 * s0;
    g_q[base + d + 32] = q1 * c1 + q0 * s1;

    float k0 = g_k[base + d], k1 = g_k[base + d + 32];
    g_k[base + d]      = k0 * c0 - k1 * s0;
    g_k[base + d + 32] = k1 * c1 + k0 * s1;
}

// ============================================================
// Flash attention (split-K, bf16x3, half-size P): unchanged R12
// ============================================================
#define AQ_H 0
#define AQ_L 4608
#define AK_H 9216
#define AK_L 10368
#define AV_H 11520
#define AV_L 12800
#define AP   14080                   // 4 warps * 640
#define ATTN_SMEM_BYTES (16640 * 4)  // 66560 B

__global__ __launch_bounds__(128, 3) void attn_bf16()
{
    uint32_t* usm = (uint32_t*)dynsm;
    uint32_t* Qh = usm + AQ_H;
    uint32_t* Ql = usm + AQ_L;
    uint32_t* Kh = usm + AK_H;
    uint32_t* Kl = usm + AK_L;
    uint32_t* Vh = usm + AV_H;
    uint32_t* Vl = usm + AV_L;

    const int h  = blockIdx.y;
    const int z  = blockIdx.z;
    const int qb = blockIdx.x * 128;
    const int tid = threadIdx.x;
    const int wid = tid >> 5, lane = tid & 31;
    const int grp = lane >> 2, tig = lane & 3;
    const int row0 = wid * 32;

    const int ktb = z * NKT0;
    const int kte = (z == 0) ? NKT0 : NKT_TOT;

    uint32_t* Ph = usm + AP + wid * 640;
    uint32_t* Pl = Ph + 320;

    const uint32_t smb = cvta_s(usm);
    const int q_lm  = AQ_H + (row0 + (lane & 15)) * 36 + (lane >> 4) * 4;
    const int q_lml = q_lm + 4608;
    const int k_lm  = AK_H + ((lane >> 4) * 8 + (lane & 7)) * 36 + ((lane >> 3) & 1) * 4;
    const int k_lml = k_lm + 1152;
    const int v_lm  = AV_H + ((lane >> 4) * 8 + (lane & 7)) * 20 + ((lane >> 3) & 1) * 4;
    const int v_lml = v_lm + 1280;
    const int p_lm  = AP + wid * 640 + (lane & 15) * 20 + (lane >> 4) * 4;
    const int p_lml = p_lm + 320;

    const float* __restrict__ Qg = g_q + (size_t)h * NPAD * DH;
    const float* __restrict__ Kg = g_k + (size_t)h * NPAD * DH;
    const float* __restrict__ Vg = g_v + (size_t)h * NPAD * DH;

#pragma unroll
    for (int t = 0; t < 16; ++t) {
        const int idx = tid + t * 128;
        const int r = idx >> 4, c4 = (idx & 15) * 4;
        float4 v = *(const float4*)(Qg + (size_t)(qb + r) * DH + c4);
        uint32_t h0, l0, h1, l1;
        split2(v.x, v.y, h0, l0);
        split2(v.z, v.w, h1, l1);
        Qh[r * 36 + c4 / 2] = h0; Qh[r * 36 + c4 / 2 + 1] = h1;
        Ql[r * 36 + c4 / 2] = l0; Ql[r * 36 + c4 / 2 + 1] = l1;
    }

    const int lr = tid >> 4;
    const int lc4 = (tid & 15) * 4;
    const int vp = tid & 15;
    const int vdg = tid >> 4;
    float4 pk[4];
    float4 ve0, ve1, vo0, vo1;

#define KV_FETCH(base) do { \
    _Pragma("unroll") \
    for (int t = 0; t < 4; ++t) \
        pk[t] = *(const float4*)(Kg + (size_t)((base) + lr + t * 8) * DH + lc4); \
    ve0 = *(const float4*)(Vg + (size_t)((base) + 2 * vp) * DH + vdg * 8); \
    ve1 = *(const float4*)(Vg + (size_t)((base) + 2 * vp) * DH + vdg * 8 + 4); \
    vo0 = *(const float4*)(Vg + (size_t)((base) + 2 * vp + 1) * DH + vdg * 8); \
    vo1 = *(const float4*)(Vg + (size_t)((base) + 2 * vp + 1) * DH + vdg * 8 + 4); \
} while (0)

#define KV_STORE() do { \
    _Pragma("unroll") \
    for (int t = 0; t < 4; ++t) { \
        const int r = lr + t * 8; \
        uint32_t h0, l0, h1, l1; \
        split2(pk[t].x, pk[t].y, h0, l0); \
        split2(pk[t].z, pk[t].w, h1, l1); \
        Kh[r * 36 + lc4 / 2] = h0; Kh[r * 36 + lc4 / 2 + 1] = h1; \
        Kl[r * 36 + lc4 / 2] = l0; Kl[r * 36 + lc4 / 2 + 1] = l1; \
    } \
    { \
        float ve[8] = {ve0.x, ve0.y, ve0.z, ve0.w, ve1.x, ve1.y, ve1.z, ve1.w}; \
        float vo[8] = {vo0.x, vo0.y, vo0.z, vo0.w, vo1.x, vo1.y, vo1.z, vo1.w}; \
        _Pragma("unroll") \
        for (int j = 0; j < 8; ++j) { \
            const int d = vdg * 8 + j; \
            uint32_t hh, ll; \
            split2(ve[j], vo[j], hh, ll); \
            Vh[d * 20 + vp] = hh; \
            Vl[d * 20 + vp] = ll; \
        } \
    } \
} while (0)

    KV_FETCH(ktb * 32);
    KV_STORE();
    __syncthreads();

    float mreg[2][2], lreg[2][2];
#pragma unroll
    for (int mt = 0; mt < 2; ++mt) {
        mreg[mt][0] = -1e38f; mreg[mt][1] = -1e38f;
        lreg[mt][0] = 0.0f;   lreg[mt][1] = 0.0f;
    }
    float o[2][8][4];
#pragma unroll
    for (int mt = 0; mt < 2; mt++)
#pragma unroll
        for (int nt = 0; nt < 8; nt++)
#pragma unroll
            for (int i = 0; i < 4; i++) o[mt][nt][i] = 0.0f;

    for (int kt = ktb; kt < kte; ++kt) {
        const int key0 = kt * 32;

        float sacc[2][4][4];
#pragma unroll
        for (int mt = 0; mt < 2; mt++)
#pragma unroll
            for (int nt = 0; nt < 4; nt++)
#pragma unroll
                for (int i = 0; i < 4; i++) sacc[mt][nt][i] = 0.0f;

#pragma unroll
        for (int ks = 0; ks < 4; ++ks) {
            const int kw = ks * 8;
            uint32_t ah[2][4], al[2][4];
#pragma unroll
            for (int mt = 0; mt < 2; ++mt) {
                LDSM_X4(ah[mt][0], ah[mt][1], ah[mt][2], ah[mt][3],
                        smb + (uint32_t)(q_lm + mt * 576 + kw) * 4u);
                LDSM_X4(al[mt][0], al[mt][1], al[mt][2], al[mt][3],
                        smb + (uint32_t)(q_lml + mt * 576 + kw) * 4u);
            }
#pragma unroll
            for (int ntp = 0; ntp < 2; ++ntp) {
                uint32_t bh0, bh1, bh2, bh3, bl0, bl1, bl2, bl3;
                LDSM_X4(bh0, bh1, bh2, bh3,
                        smb + (uint32_t)(k_lm + ntp * 16 * 36 + kw) * 4u);
                LDSM_X4(bl0, bl1, bl2, bl3,
                        smb + (uint32_t)(k_lml + ntp * 16 * 36 + kw) * 4u);
#pragma unroll
                for (int mt = 0; mt < 2; ++mt) {
                    MMA_BF16(sacc[mt][2 * ntp], ah[mt][0], ah[mt][1], ah[mt][2], ah[mt][3], bh0, bh1);
                    MMA_BF16(sacc[mt][2 * ntp], ah[mt][0], ah[mt][1], ah[mt][2], ah[mt][3], bl0, bl1);
                    MMA_BF16(sacc[mt][2 * ntp], al[mt][0], al[mt][1], al[mt][2], al[mt][3], bh0, bh1);
                    MMA_BF16(sacc[mt][2 * ntp + 1], ah[mt][0], ah[mt][1], ah[mt][2], ah[mt][3], bh2, bh3);
                    MMA_BF16(sacc[mt][2 * ntp + 1], ah[mt][0], ah[mt][1], ah[mt][2], ah[mt][3], bl2, bl3);
                    MMA_BF16(sacc[mt][2 * ntp + 1], al[mt][0], al[mt][1], al[mt][2], al[mt][3], bh2, bh3);
                }
            }
        }

        if (kt + 1 < kte) KV_FETCH((kt + 1) * 32);

#pragma unroll
        for (int mt = 0; mt < 2; ++mt) {
            float mx0 = -1e30f, mx1 = -1e30f;
#pragma unroll
            for (int nt = 0; nt < 4; ++nt) {
                const int c0 = key0 + nt * 8 + tig * 2;
                if (c0 >= NSEQ)     { sacc[mt][nt][0] = -1e30f; sacc[mt][nt][2] = -1e30f; }
                if (c0 + 1 >= NSEQ) { sacc[mt][nt][1] = -1e30f; sacc[mt][nt][3] = -1e30f; }
                mx0 = fmaxf(mx0, fmaxf(sacc[mt][nt][0], sacc[mt][nt][1]));
                mx1 = fmaxf(mx1, fmaxf(sacc[mt][nt][2], sacc[mt][nt][3]));
            }
            mx0 = fmaxf(mx0, __shfl_xor_sync(0xffffffffu, mx0, 1));
            mx0 = fmaxf(mx0, __shfl_xor_sync(0xffffffffu, mx0, 2));
            mx1 = fmaxf(mx1, __shfl_xor_sync(0xffffffffu, mx1, 1));
            mx1 = fmaxf(mx1, __shfl_xor_sync(0xffffffffu, mx1, 2));

            const float mn0 = fmaxf(mreg[mt][0], mx0);
            const float mn1 = fmaxf(mreg[mt][1], mx1);
            const float a0 = __expf(mreg[mt][0] - mn0);
            const float a1 = __expf(mreg[mt][1] - mn1);
            mreg[mt][0] = mn0; mreg[mt][1] = mn1;

            float s0 = 0.0f, s1 = 0.0f;
#pragma unroll
            for (int nt = 0; nt < 4; ++nt) {
                sacc[mt][nt][0] = __expf(sacc[mt][nt][0] - mn0); s0 += sacc[mt][nt][0];
                sacc[mt][nt][1] = __expf(sacc[mt][nt][1] - mn0); s0 += sacc[mt][nt][1];
                sacc[mt][nt][2] = __expf(sacc[mt][nt][2] - mn1); s1 += sacc[mt][nt][2];
                sacc[mt][nt][3] = __expf(sacc[mt][nt][3] - mn1); s1 += sacc[mt][nt][3];
            }
            s0 += __shfl_xor_sync(0xffffffffu, s0, 1);
            s0 += __shfl_xor_sync(0xffffffffu, s0, 2);
            s1 += __shfl_xor_sync(0xffffffffu, s1, 1);
            s1 += __shfl_xor_sync(0xffffffffu, s1, 2);
            lreg[mt][0] = lreg[mt][0] * a0 + s0;
            lreg[mt][1] = lreg[mt][1] * a1 + s1;

#pragma unroll
            for (int nt = 0; nt < 4; ++nt) {
                const int cw = nt * 4 + tig;
                uint32_t hh, ll;
                split2(sacc[mt][nt][0], sacc[mt][nt][1], hh, ll);
                Ph[grp * 20 + cw] = hh; Pl[grp * 20 + cw] = ll;
                split2(sacc[mt][nt][2], sacc[mt][nt][3], hh, ll);
                Ph[(grp + 8) * 20 + cw] = hh; Pl[(grp + 8) * 20 + cw] = ll;
            }

#pragma unroll
            for (int nt = 0; nt < 8; ++nt) {
                o[mt][nt][0] *= a0; o[mt][nt][1] *= a0;
                o[mt][nt][2] *= a1; o[mt][nt][3] *= a1;
            }
            __syncwarp();

#pragma unroll
            for (int kk = 0; kk < 2; ++kk) {
                const int kw = kk * 8;
                uint32_t ph0, ph1, ph2, ph3, pl0, pl1, pl2, pl3;
                LDSM_X4(ph0, ph1, ph2, ph3, smb + (uint32_t)(p_lm + kw) * 4u);
                LDSM_X4(pl0, pl1, pl2, pl3, smb + (uint32_t)(p_lml + kw) * 4u);
#pragma unroll
                for (int ntp = 0; ntp < 4; ++ntp) {
                    uint32_t vh0, vh1, vh2, vh3, vl0, vl1, vl2, vl3;
                    LDSM_X4(vh0, vh1, vh2, vh3,
                            smb + (uint32_t)(v_lm + ntp * 16 * 20 + kw) * 4u);
                    LDSM_X4(vl0, vl1, vl2, vl3,
                            smb + (uint32_t)(v_lml + ntp * 16 * 20 + kw) * 4u);
                    MMA_BF16(o[mt][2 * ntp], ph0, ph1, ph2, ph3, vh0, vh1);
                    MMA_BF16(o[mt][2 * ntp], ph0, ph1, ph2, ph3, vl0, vl1);
                    MMA_BF16(o[mt][2 * ntp], pl0, pl1, pl2, pl3, vh0, vh1);
                    MMA_BF16(o[mt][2 * ntp + 1], ph0, ph1, ph2, ph3, vh2, vh3);
                    MMA_BF16(o[mt][2 * ntp + 1], ph0, ph1, ph2, ph3, vl2, vl3);
                    MMA_BF16(o[mt][2 * ntp + 1], pl0, pl1, pl2, pl3, vh2, vh3);
                }
            }
            if (mt == 0) __syncwarp();
        }
        __syncthreads();

        if (kt + 1 < kte) {
            KV_STORE();
            __syncthreads();
        }
    }

    float* __restrict__ part = g_part + (size_t)(z * NH + h) * NPAD * DH;
    float2* __restrict__ mlp = g_ml + (size_t)(z * NH + h) * NPAD;
#pragma unroll
    for (int mt = 0; mt < 2; ++mt) {
        const float inv0 = 1.0f / lreg[mt][0];
        const float inv1 = 1.0f / lreg[mt][1];
        const int n0 = qb + row0 + mt * 16 + grp;
        const int n1 = n0 + 8;
        if (tig == 0) {
            if (n0 < NSEQ) mlp[n0] = make_float2(mreg[mt][0], lreg[mt][0]);
            if (n1 < NSEQ) mlp[n1] = make_float2(mreg[mt][1], lreg[mt][1]);
        }
#pragma unroll
        for (int nt = 0; nt < 8; ++nt) {
            const int col = nt * 8 + tig * 2;
            if (n0 < NSEQ)
                *(float2*)&part[(size_t)n0 * DH + col] =
                    make_float2(o[mt][nt][0] * inv0, o[mt][nt][1] * inv0);
            if (n1 < NSEQ)
                *(float2*)&part[(size_t)n1 * DH + col] =
                    make_float2(o[mt][nt][2] * inv1, o[mt][nt][3] * inv1);
        }
    }
}

// ============================================================
// Combine split-K partials -> g_attn
// ============================================================
__global__ void attn_combine()
{
    const int t = blockIdx.x * blockDim.x + threadIdx.x;
    if (t >= NH * NSEQ * 16) return;
    const int d4 = (t & 15) * 4;
    const int n = (t >> 4) % NSEQ;
    const int h = t / (16 * NSEQ);

    const float2 ml0 = g_ml[(size_t)(0 * NH + h) * NPAD + n];
    const float2 ml1 = g_ml[(size_t)(1 * NH + h) * NPAD + n];
    const float m = fmaxf(ml0.x, ml1.x);
    float w0 = ml0.y * __expf(ml0.x - m);
    float w1 = ml1.y * __expf(ml1.x - m);
    const float inv = 1.0f / (w0 + w1);
    w0 *= inv; w1 *= inv;

    const float4 o0 = *(const float4*)&g_part[((size_t)(0 * NH + h) * NPAD + n) * DH + d4];
    const float4 o1 = *(const float4*)&g_part[((size_t)(1 * NH + h) * NPAD + n) * DH + d4];
    float4 r;
    r.x = w0 * o0.x + w1 * o1.x;
    r.y = w0 * o0.y + w1 * o1.y;
    r.z = w0 * o0.z + w1 * o1.z;
    r.w = w0 * o0.w + w1 * o1.w;
    *(float4*)&g_attn[(size_t)n * DIMF + h * DH + d4] = r;
}

// ============================================================
extern "C" void kernel_launch(void* const* d_in, const int* in_sizes, int n_in,
                              void* d_out, int out_size)
{
    (void)in_sizes; (void)n_in; (void)out_size;
    const float* x     = (const float*)d_in[0];
    const float* rope  = (const float*)d_in[1];
    const float* Wqkv  = (const float*)d_in[2];
    const float* Wproj = (const float*)d_in[3];
    const float* bproj = (const float*)d_in[4];
    float* out = (float*)d_out;

    static int configured = 0;
    if (!configured) {
        cudaFuncSetAttribute(gemm_qkv_kern,  cudaFuncAttributeMaxDynamicSharedMemorySize, GSMEM_QK);
        cudaFuncSetAttribute(gemm_proj_kern, cudaFuncAttributeMaxDynamicSharedMemorySize, GSMEM_QK);
        cudaFuncSetAttribute(attn_bf16,      cudaFuncAttributeMaxDynamicSharedMemorySize, ATTN_SMEM_BYTES);
        configured = 1;
    }

    gemm_qkv_kern<<<dim3(24, 13), 256, GSMEM_QK>>>(x, Wqkv);
    rope_kernel<<<(HWLEN * NH * 32 + 255) / 256, 256>>>(rope);
    attn_bf16<<<dim3(13, NH, NSPLIT), 128, ATTN_SMEM_BYTES>>>();
    attn_combine<<<(NH * NSEQ * 16 + 255) / 256, 256>>>();
    gemm_proj_kern<<<dim3(8, 13), 256, GSMEM_QK>>>(Wproj, bproj, out);
}